// round 15
// baseline (speedup 1.0000x reference)
#include <cuda_runtime.h>
#include <cstdint>

#define H 4096
#define NUM_LAYERS 8
#define NBLOCKS 256
#define NTHREADS 512          // 16 warps -> 4096 warps == one per row
#define WARPS (NTHREADS / 32)

// Ping-pong hidden-state buffers (allocation-free scratch).
__device__ float g_h[2][H];

// Software grid-barrier state (monotonic across graph replays).
__device__ unsigned g_bar_count = 0;
__device__ unsigned g_bar_phase = 0;

// Grid-wide barrier. Safe: 256 blocks <= 148 SMs * 2 (enforced by
// __launch_bounds__(512, 2)), all co-resident.
__device__ __forceinline__ void grid_barrier() {
    __syncthreads();
    if (threadIdx.x == 0) {
        const unsigned target = *(volatile unsigned*)&g_bar_phase + 1;
        __threadfence();
        const unsigned old = atomicAdd(&g_bar_count, 1);
        if (old == NBLOCKS - 1) {
            *(volatile unsigned*)&g_bar_count = 0;
            __threadfence();
            atomicAdd(&g_bar_phase, 1);
        } else {
            while (*(volatile unsigned*)&g_bar_phase < target)
                __nanosleep(64);
        }
        __threadfence();
    }
    __syncthreads();
}

// L2-scoped vector load (bypasses L1: coherent with just-written h, and no
// L1tex allocation for the shared x vector).
__device__ __forceinline__ float4 ldg_cg4(const float4* p) {
    float4 v;
    asm volatile("ld.global.cg.v4.f32 {%0,%1,%2,%3}, [%4];"
                 : "=f"(v.x), "=f"(v.y), "=f"(v.z), "=f"(v.w) : "l"(p));
    return v;
}

// Persistent fused RNN (R8 winner structure) minus the per-layer x staging:
// x/h is read directly from L2 (ld.global.cg) interleaved with the weight
// batches, so the first weight LDG.128 issues immediately after the grid
// barrier instead of waiting behind a 16KB smem stage + __syncthreads.
__global__ void __launch_bounds__(NTHREADS, 2)
rnn_fused_kernel(const float* __restrict__ x,
                 const float* __restrict__ Wxh,
                 const float* __restrict__ bxh,
                 const float* __restrict__ bhh,
                 const float* __restrict__ fc_w,
                 const float* __restrict__ fc_b,
                 float* __restrict__ out) {
    const int warp = threadIdx.x >> 5;
    const int lane = threadIdx.x & 31;
    const int row  = blockIdx.x * WARPS + warp;   // 0..4095

    const float* cur = x;

    #pragma unroll 1
    for (int l = 0; l <= NUM_LAYERS; l++) {        // 8 tanh layers + fc
        const bool last = (l == NUM_LAYERS);
        const float* Wl = last ? fc_w : Wxh + (size_t)l * H * H;

        const float4* Wr  = reinterpret_cast<const float4*>(Wl + (size_t)row * H);
        const float4* xv4 = reinterpret_cast<const float4*>(cur);

        float acc[4] = {0.f, 0.f, 0.f, 0.f};
        #pragma unroll
        for (int i = 0; i < 32; i += 4) {
            float4 w[4];
            #pragma unroll
            for (int j = 0; j < 4; j++)            // 4 independent DRAM loads
                w[j] = Wr[lane + (i + j) * 32];
            float4 xr[4];
            #pragma unroll
            for (int j = 0; j < 4; j++)            // 4 L2-hit loads
                xr[j] = ldg_cg4(&xv4[lane + (i + j) * 32]);
            #pragma unroll
            for (int j = 0; j < 4; j++)
                acc[j] += w[j].x * xr[j].x + w[j].y * xr[j].y
                        + w[j].z * xr[j].z + w[j].w * xr[j].w;
        }

        float a = (acc[0] + acc[1]) + (acc[2] + acc[3]);
        #pragma unroll
        for (int off = 16; off; off >>= 1)
            a += __shfl_down_sync(0xffffffffu, a, off);

        if (last) {
            if (lane == 0)
                out[row] = a + fc_b[row];
        } else {
            if (lane == 0)
                g_h[l & 1][row] = tanhf(a + bxh[l * H + row] + bhh[l * H + row]);
            grid_barrier();           // publish h before anyone reads it
            cur = g_h[l & 1];
        }
    }
}

extern "C" void kernel_launch(void* const* d_in, const int* in_sizes, int n_in,
                              void* d_out, int out_size) {
    const float* x    = (const float*)d_in[0];  // [1, H]
    const float* Wxh  = (const float*)d_in[1];  // [L, H, H]
    const float* bxh  = (const float*)d_in[2];  // [L, H]
    // d_in[3] = Whh — multiplied by a zero vector in the reference; never read.
    const float* bhh  = (const float*)d_in[4];  // [L, H]
    const float* fc_w = (const float*)d_in[5];  // [H, H]
    const float* fc_b = (const float*)d_in[6];  // [H]
    float* out = (float*)d_out;

    rnn_fused_kernel<<<NBLOCKS, NTHREADS>>>(x, Wxh, bxh, bhh, fc_w, fc_b, out);
}

// round 16
// speedup vs baseline: 1.2753x; 1.2753x over previous
#include <cuda_runtime.h>
#include <cstdint>

#define H 4096
#define NUM_LAYERS 8
#define NBLOCKS 256
#define NTHREADS 512          // 16 warps -> 4096 warps == one per row
#define WARPS (NTHREADS / 32)

// Ping-pong hidden-state buffers (allocation-free scratch).
__device__ float g_h[2][H];

// Software grid-barrier state (monotonic across graph replays).
__device__ unsigned g_bar_count = 0;
__device__ unsigned g_bar_phase = 0;

// Grid-wide barrier. Safe because all NBLOCKS are co-resident
// (NBLOCKS=256 <= 148 SMs * 2 blocks, enforced by __launch_bounds__(512,2)).
__device__ __forceinline__ void grid_barrier() {
    __syncthreads();
    if (threadIdx.x == 0) {
        const unsigned target = *(volatile unsigned*)&g_bar_phase + 1;
        __threadfence();
        const unsigned old = atomicAdd(&g_bar_count, 1);
        if (old == NBLOCKS - 1) {
            *(volatile unsigned*)&g_bar_count = 0;
            __threadfence();
            atomicAdd(&g_bar_phase, 1);
        } else {
            while (*(volatile unsigned*)&g_bar_phase < target)
                __nanosleep(32);      // short wakeup: spin latency sits on the seam
        }
        __threadfence();
    }
    __syncthreads();
}

// One warp computes dot(W[row,:], x_smem) with the batch-4 LDG.128 schedule
// (4 independent loads in flight, 64 regs) — the empirically optimal shape.
__device__ __forceinline__ float row_dot(const float* __restrict__ W,
                                         const float4* __restrict__ sh4,
                                         int row, int lane) {
    const float4* Wr = reinterpret_cast<const float4*>(W + (size_t)row * H);
    float acc[4] = {0.f, 0.f, 0.f, 0.f};
    #pragma unroll
    for (int i = 0; i < 32; i += 4) {
        float4 w[4];
        #pragma unroll
        for (int j = 0; j < 4; j++)
            w[j] = Wr[lane + (i + j) * 32];
        #pragma unroll
        for (int j = 0; j < 4; j++) {
            float4 xv = sh4[lane + (i + j) * 32];
            acc[j] += w[j].x * xv.x + w[j].y * xv.y
                    + w[j].z * xv.z + w[j].w * xv.w;
        }
    }
    float a = (acc[0] + acc[1]) + (acc[2] + acc[3]);
    #pragma unroll
    for (int off = 16; off; off >>= 1)
        a += __shfl_down_sync(0xffffffffu, a, off);
    return a;
}

// Whole network in one persistent kernel: 8 tanh layers + final fc.
// Exactly one warp per output row per layer (4096 warps); layers separated
// by a software grid barrier instead of kernel launches. 256 blocks = 2 per
// SM so one block streams weights while its SM-sibling spins at the barrier
// (seam overlap) — the configuration that every measured variant around it
// (geometry, prefetch, dataflow, no-smem-x) failed to beat.
__global__ void __launch_bounds__(NTHREADS, 2)
rnn_fused_kernel(const float* __restrict__ x,
                 const float* __restrict__ Wxh,
                 const float* __restrict__ bxh,
                 const float* __restrict__ bhh,
                 const float* __restrict__ fc_w,
                 const float* __restrict__ fc_b,
                 float* __restrict__ out) {
    __shared__ float4 sh4[H / 4];   // 16 KB: current input vector

    const int warp = threadIdx.x >> 5;
    const int lane = threadIdx.x & 31;
    const int row  = blockIdx.x * WARPS + warp;   // 0..4095

    const float* cur = x;

    #pragma unroll 1
    for (int l = 0; l < NUM_LAYERS; l++) {
        // Stage the layer input (16 KB) into shared memory.
        const float4* xg = reinterpret_cast<const float4*>(cur);
        #pragma unroll
        for (int i = threadIdx.x; i < H / 4; i += NTHREADS)
            sh4[i] = xg[i];
        __syncthreads();

        const float a = row_dot(Wxh + (size_t)l * H * H, sh4, row, lane);
        if (lane == 0)
            g_h[l & 1][row] = tanhf(a + bxh[l * H + row] + bhh[l * H + row]);

        grid_barrier();               // publish h before anyone reads it
        cur = g_h[l & 1];
    }

    // Final linear layer (no tanh, single bias) -> d_out.
    {
        const float4* xg = reinterpret_cast<const float4*>(cur);
        #pragma unroll
        for (int i = threadIdx.x; i < H / 4; i += NTHREADS)
            sh4[i] = xg[i];
        __syncthreads();

        const float a = row_dot(fc_w, sh4, row, lane);
        if (lane == 0)
            out[row] = a + fc_b[row];
    }
}

extern "C" void kernel_launch(void* const* d_in, const int* in_sizes, int n_in,
                              void* d_out, int out_size) {
    const float* x    = (const float*)d_in[0];  // [1, H]
    const float* Wxh  = (const float*)d_in[1];  // [L, H, H]
    const float* bxh  = (const float*)d_in[2];  // [L, H]
    // d_in[3] = Whh — multiplied by a zero vector in the reference; never read.
    const float* bhh  = (const float*)d_in[4];  // [L, H]
    const float* fc_w = (const float*)d_in[5];  // [H, H]
    const float* fc_b = (const float*)d_in[6];  // [H]
    float* out = (float*)d_out;

    rnn_fused_kernel<<<NBLOCKS, NTHREADS>>>(x, Wxh, bxh, bhh, fc_w, fc_b, out);
}